// round 12
// baseline (speedup 1.0000x reference)
#include <cuda_runtime.h>
#include <math.h>
#include <stdint.h>

typedef unsigned long long ull;

// ---------------------------------------------------------------- constants
constexpr int BATCH = 64;
constexpr int SEQ   = 512;
constexpr int WIDTH = 256;   // hidden width
constexpr int EMBED = 512;   // 2*WIDTH
constexpr int ROWS  = BATCH * SEQ;   // 32768 GEMM rows

// ---------------------------------------------------------------- scratch
__device__ float g_bufA[BATCH * SEQ * WIDTH];
__device__ float g_bufB[BATCH * SEQ * WIDTH];

// ---------------------------------------------------------------- f32x2 helpers
__device__ __forceinline__ ull pk2(float lo, float hi) {
    ull r; asm("mov.b64 %0,{%1,%2};" : "=l"(r) : "f"(lo), "f"(hi)); return r;
}
__device__ __forceinline__ void up2(ull v, float& lo, float& hi) {
    asm("mov.b64 {%0,%1},%2;" : "=f"(lo), "=f"(hi) : "l"(v));
}
__device__ __forceinline__ ull ffma2(ull a, ull b, ull c) {
    ull d; asm("fma.rn.f32x2 %0,%1,%2,%3;" : "=l"(d) : "l"(a), "l"(b), "l"(c)); return d;
}
__device__ __forceinline__ uint32_t smem_u32(const void* p) {
    uint32_t a;
    asm("{ .reg .u64 t; cvta.to.shared.u64 t, %1; cvt.u32.u64 %0, t; }"
        : "=r"(a) : "l"(p));
    return a;
}
__device__ __forceinline__ void mbar_wait(uint32_t mb, uint32_t parity) {
    uint32_t done;
    asm volatile(
        "{\n\t.reg .pred p;\n\t"
        "mbarrier.try_wait.parity.acquire.cta.shared::cta.b64 p, [%1], %2;\n\t"
        "selp.b32 %0, 1, 0, p;\n\t}"
        : "=r"(done) : "r"(mb), "r"(parity) : "memory");
    if (!done) {
        asm volatile(
            "{\n\t.reg .pred P1;\n\t"
            "WL_%=:\n\t"
            "mbarrier.try_wait.parity.acquire.cta.shared::cta.b64 P1, [%0], %1, 0x989680;\n\t"
            "@P1 bra.uni WD_%=;\n\t"
            "bra.uni WL_%=;\n\t"
            "WD_%=:\n\t}"
            :: "r"(mb), "r"(parity) : "memory");
    }
}

// ============================================================================
// GEMM: C[R, 256] = A[R, K] @ Wm[K, 256] + bias   (byte-identical to R10)
// ============================================================================
constexpr int GK = 32;
constexpr int BS_STR = 132;
constexpr size_t GEMM_SMEM = (size_t)GK * 128 * 8
                           + (size_t)GK * BS_STR * 4;

template<bool GATHER>
__global__ void __launch_bounds__(512, 1)
gemm_kernel(const int* __restrict__ tokens, const float* __restrict__ A,
            const float* __restrict__ Wm, const float* __restrict__ bias,
            float* __restrict__ C, int K)
{
    extern __shared__ unsigned char gsm[];
    ull*   ATu = (ull*)gsm;
    float* Bs  = (float*)(gsm + (size_t)GK * 128 * 8);

    const int tid = threadIdx.x;
    const int r0  = blockIdx.x * 128;
    const int n0  = blockIdx.y * 128;

    const int lrow = tid >> 2;
    const int lk8  = (tid & 3) * 8;
    const float* arow;
    if (GATHER) arow = A + (size_t)tokens[r0 + lrow] * (size_t)K;
    else        arow = A + (size_t)(r0 + lrow) * (size_t)K;

    const int bk = tid >> 4;
    const int bn = (tid & 15) * 8;

    const int ty = tid >> 5;
    const int tx = tid & 31;
    const int cm = ty * 8;
    const int cn = tx * 4;

    ull acc[8][2];
    #pragma unroll
    for (int r = 0; r < 8; r++) { acc[r][0] = 0ull; acc[r][1] = 0ull; }

    float4 a0v = *(const float4*)(arow + lk8);
    float4 a1v = *(const float4*)(arow + lk8 + 4);
    float4 b0v = *(const float4*)(Wm + (size_t)bk * WIDTH + n0 + bn);
    float4 b1v = *(const float4*)(Wm + (size_t)bk * WIDTH + n0 + bn + 4);

    #pragma unroll 1
    for (int k0 = 0; k0 < K; k0 += GK) {
        __syncthreads();
        ATu[(lk8 + 0) * 128 + lrow] = pk2(a0v.x, a0v.x);
        ATu[(lk8 + 1) * 128 + lrow] = pk2(a0v.y, a0v.y);
        ATu[(lk8 + 2) * 128 + lrow] = pk2(a0v.z, a0v.z);
        ATu[(lk8 + 3) * 128 + lrow] = pk2(a0v.w, a0v.w);
        ATu[(lk8 + 4) * 128 + lrow] = pk2(a1v.x, a1v.x);
        ATu[(lk8 + 5) * 128 + lrow] = pk2(a1v.y, a1v.y);
        ATu[(lk8 + 6) * 128 + lrow] = pk2(a1v.z, a1v.z);
        ATu[(lk8 + 7) * 128 + lrow] = pk2(a1v.w, a1v.w);
        *(float4*)&Bs[bk * BS_STR + bn]     = b0v;
        *(float4*)&Bs[bk * BS_STR + bn + 4] = b1v;
        __syncthreads();

        if (k0 + GK < K) {
            a0v = *(const float4*)(arow + k0 + GK + lk8);
            a1v = *(const float4*)(arow + k0 + GK + lk8 + 4);
            b0v = *(const float4*)(Wm + (size_t)(k0 + GK + bk) * WIDTH + n0 + bn);
            b1v = *(const float4*)(Wm + (size_t)(k0 + GK + bk) * WIDTH + n0 + bn + 4);
        }

        #pragma unroll
        for (int kk = 0; kk < GK; kk++) {
            ulonglong2 bv = *(const ulonglong2*)&Bs[kk * BS_STR + cn];
            const ull* arow_s = &ATu[kk * 128 + cm];
            ulonglong2 ad01 = *(const ulonglong2*)(arow_s + 0);
            ulonglong2 ad23 = *(const ulonglong2*)(arow_s + 2);
            ulonglong2 ad45 = *(const ulonglong2*)(arow_s + 4);
            ulonglong2 ad67 = *(const ulonglong2*)(arow_s + 6);
            acc[0][0] = ffma2(ad01.x, bv.x, acc[0][0]);
            acc[0][1] = ffma2(ad01.x, bv.y, acc[0][1]);
            acc[1][0] = ffma2(ad01.y, bv.x, acc[1][0]);
            acc[1][1] = ffma2(ad01.y, bv.y, acc[1][1]);
            acc[2][0] = ffma2(ad23.x, bv.x, acc[2][0]);
            acc[2][1] = ffma2(ad23.x, bv.y, acc[2][1]);
            acc[3][0] = ffma2(ad23.y, bv.x, acc[3][0]);
            acc[3][1] = ffma2(ad23.y, bv.y, acc[3][1]);
            acc[4][0] = ffma2(ad45.x, bv.x, acc[4][0]);
            acc[4][1] = ffma2(ad45.x, bv.y, acc[4][1]);
            acc[5][0] = ffma2(ad45.y, bv.x, acc[5][0]);
            acc[5][1] = ffma2(ad45.y, bv.y, acc[5][1]);
            acc[6][0] = ffma2(ad67.x, bv.x, acc[6][0]);
            acc[6][1] = ffma2(ad67.x, bv.y, acc[6][1]);
            acc[7][0] = ffma2(ad67.y, bv.x, acc[7][0]);
            acc[7][1] = ffma2(ad67.y, bv.y, acc[7][1]);
        }
    }

    const float bv0 = bias[n0 + cn + 0];
    const float bv1 = bias[n0 + cn + 1];
    const float bv2 = bias[n0 + cn + 2];
    const float bv3 = bias[n0 + cn + 3];
    #pragma unroll
    for (int r = 0; r < 8; r++) {
        float c0, c1, c2, c3;
        up2(acc[r][0], c0, c1);
        up2(acc[r][1], c2, c3);
        float4 o = make_float4(c0 + bv0, c1 + bv1, c2 + bv2, c3 + bv3);
        *(float4*)&C[(size_t)(r0 + cm + r) * WIDTH + n0 + cn] = o;
    }
}

// ============================================================================
// RNN scan, cluster-of-2 per TWO batch rows (dual independent chains).
//  - cluster handles rows b0=2*cb, b1=2*cb+1; U registers shared across rows
//  - rank owns output columns [rank*128, rank*128+128)
//  - 256 threads: column j = rank*128 + (tid>>1), k-half = tid&1
//  - per thread: 32 local-range + 32 peer-range U pairs in registers
//  - mbarL/mbarP per phase expect 1024 B (both rows' 128 floats each)
//  - row1's compute hides row0's DSMEM flight and vice versa
// ============================================================================
constexpr int HSTR = 264;    // floats per h buffer per row

template<bool WRITE_SEQ, bool FINAL>
__global__ void __launch_bounds__(256, 1) __cluster_dims__(2, 1, 1)
rnn_kernel(const float* __restrict__ xw, const float* __restrict__ U,
           float* __restrict__ hs, const float* __restrict__ Wd,
           const float* __restrict__ bd, float* __restrict__ out)
{
    __shared__ __align__(16) float hbuf[2][2][HSTR];  // [phase][row][col]
    __shared__ __align__(8)  ull mbars[4];   // [0..1]=mbarL phases, [2..3]=mbarP
    __shared__ float red[2 * WIDTH];

    const int tid = threadIdx.x;
    uint32_t rank;
    asm("mov.u32 %0, %%cluster_ctarank;" : "=r"(rank));
    const int cb   = blockIdx.x >> 1;      // cluster index: rows 2cb, 2cb+1
    const int half = tid & 1;
    const int jl   = tid >> 1;             // 0..127
    const int j    = (int)rank * 128 + jl; // global column

    const int kbL = (int)rank * 128 + half * 64;
    const int kbP = (int)(rank ^ 1u) * 128 + half * 64;

    // ---- U pairs in registers (shared by both rows)
    ull uL[32], uP[32];
    #pragma unroll
    for (int m = 0; m < 32; m++) {
        uL[m] = pk2(U[(size_t)(kbL + 2 * m) * WIDTH + j],
                    U[(size_t)(kbL + 2 * m + 1) * WIDTH + j]);
        uP[m] = pk2(U[(size_t)(kbP + 2 * m) * WIDTH + j],
                    U[(size_t)(kbP + 2 * m + 1) * WIDTH + j]);
    }

    // ---- init phase-0 buffers (both rows) + mbars
    for (int i = tid; i < 2 * HSTR; i += 256) ((float*)hbuf[0])[i] = 0.0f;
    if (tid == 0) {
        #pragma unroll
        for (int i = 0; i < 4; i++)
            asm volatile("mbarrier.init.shared.b64 [%0], %1;"
                         :: "r"(smem_u32(&mbars[i])), "r"(1) : "memory");
    }
    __syncthreads();
    asm volatile("barrier.cluster.arrive.aligned;" ::: "memory");
    asm volatile("barrier.cluster.wait.aligned;" ::: "memory");

    const uint32_t hbuf_u32 = smem_u32(&hbuf[0][0][0]);
    const uint32_t mbar_u32 = smem_u32(&mbars[0]);
    uint32_t self_hbuf, self_mbar, peer_hbuf, peer_mbar;
    {
        uint32_t sr = rank, pr = rank ^ 1u;
        asm("mapa.shared::cluster.u32 %0, %1, %2;" : "=r"(self_hbuf) : "r"(hbuf_u32), "r"(sr));
        asm("mapa.shared::cluster.u32 %0, %1, %2;" : "=r"(self_mbar) : "r"(mbar_u32), "r"(sr));
        asm("mapa.shared::cluster.u32 %0, %1, %2;" : "=r"(peer_hbuf) : "r"(hbuf_u32), "r"(pr));
        asm("mapa.shared::cluster.u32 %0, %1, %2;" : "=r"(peer_mbar) : "r"(mbar_u32), "r"(pr));
    }

    const float* xb0 = xw + (size_t)(2 * cb + 0) * SEQ * WIDTH + j;
    const float* xb1 = xw + (size_t)(2 * cb + 1) * SEQ * WIDTH + j;
    float x0n = xb0[0];
    float x1n = xb1[0];

    #pragma unroll 1
    for (int t = 0; t < SEQ; t++) {
        const int rd = t & 1;
        const int wr = rd ^ 1;
        const uint32_t slot  = (uint32_t)(t & 1) * 8;
        const uint32_t pslot = (uint32_t)((t ^ 1) & 1) * 8;
        const uint32_t ppar  = (uint32_t)(((t - 1) >> 1) & 1);

        if (tid == 0) {
            asm volatile("mbarrier.arrive.expect_tx.shared.b64 _, [%0], %1;"
                         :: "r"(mbar_u32 + slot), "r"(1024) : "memory");       // mbarL
            asm volatile("mbarrier.arrive.expect_tx.shared.b64 _, [%0], %1;"
                         :: "r"(mbar_u32 + 16 + slot), "r"(1024) : "memory");  // mbarP
        }

        const float x0 = x0n, x1 = x1n;
        if (t + 1 < SEQ) {
            x0n = xb0[(size_t)(t + 1) * WIDTH];
            x1n = xb1[(size_t)(t + 1) * WIDTH];
        }

        ull r0a0 = 0ull, r0a1 = 0ull, r0a2 = 0ull, r0a3 = 0ull;
        ull r1a0 = 0ull, r1a1 = 0ull, r1a2 = 0ull, r1a3 = 0ull;

        // ---- phase 1: local-range pairs, both rows
        if (t > 0) mbar_wait(mbar_u32 + pslot, ppar);          // mbarL[prev]
        {
            const ull* h0 = (const ull*)&hbuf[rd][0][0] + (kbL >> 1);
            const ull* h1 = (const ull*)&hbuf[rd][1][0] + (kbL >> 1);
            #pragma unroll
            for (int m = 0; m < 32; m += 2) {
                ulonglong2 p0 = *(const ulonglong2*)(h0 + m);
                ulonglong2 p1 = *(const ulonglong2*)(h1 + m);
                r0a0 = ffma2(p0.x, uL[m + 0], r0a0);
                r0a1 = ffma2(p0.y, uL[m + 1], r0a1);
                r1a0 = ffma2(p1.x, uL[m + 0], r1a0);
                r1a1 = ffma2(p1.y, uL[m + 1], r1a1);
            }
        }

        // ---- phase 2: peer-range pairs, both rows (flight overlapped)
        if (t > 0) mbar_wait(mbar_u32 + 16 + pslot, ppar);     // mbarP[prev]
        {
            const ull* h0 = (const ull*)&hbuf[rd][0][0] + (kbP >> 1);
            const ull* h1 = (const ull*)&hbuf[rd][1][0] + (kbP >> 1);
            #pragma unroll
            for (int m = 0; m < 32; m += 2) {
                ulonglong2 p0 = *(const ulonglong2*)(h0 + m);
                ulonglong2 p1 = *(const ulonglong2*)(h1 + m);
                r0a2 = ffma2(p0.x, uP[m + 0], r0a2);
                r0a3 = ffma2(p0.y, uP[m + 1], r0a3);
                r1a2 = ffma2(p1.x, uP[m + 0], r1a2);
                r1a3 = ffma2(p1.y, uP[m + 1], r1a3);
            }
        }

        float s0, s1, s2, s3, s4, s5, s6, s7;
        up2(r0a0, s0, s1); up2(r0a1, s2, s3); up2(r0a2, s4, s5); up2(r0a3, s6, s7);
        float sA = (((s0 + s1) + (s2 + s3)) + ((s4 + s5) + (s6 + s7)));
        up2(r1a0, s0, s1); up2(r1a1, s2, s3); up2(r1a2, s4, s5); up2(r1a3, s6, s7);
        float sB = (((s0 + s1) + (s2 + s3)) + ((s4 + s5) + (s6 + s7)));
        sA += __shfl_xor_sync(0xFFFFFFFFu, sA, 1);
        sB += __shfl_xor_sync(0xFFFFFFFFu, sB, 1);

        const float eA = __expf(2.0f * (x0 + sA));
        const float h0n = 1.0f - __fdividef(2.0f, eA + 1.0f);
        const float eB = __expf(2.0f * (x1 + sB));
        const float h1n = 1.0f - __fdividef(2.0f, eB + 1.0f);

        if (half == 0) {
            const uint32_t off0 = (uint32_t)((wr * 2 + 0) * HSTR * 4 + j * 4);
            const uint32_t off1 = (uint32_t)((wr * 2 + 1) * HSTR * 4 + j * 4);
            const uint32_t b0 = __float_as_uint(h0n);
            const uint32_t b1 = __float_as_uint(h1n);
            asm volatile(
                "st.async.shared::cluster.mbarrier::complete_tx::bytes.b32 [%0], %1, [%2];"
                :: "r"(self_hbuf + off0), "r"(b0), "r"(self_mbar + slot) : "memory");
            asm volatile(
                "st.async.shared::cluster.mbarrier::complete_tx::bytes.b32 [%0], %1, [%2];"
                :: "r"(self_hbuf + off1), "r"(b1), "r"(self_mbar + slot) : "memory");
            asm volatile(
                "st.async.shared::cluster.mbarrier::complete_tx::bytes.b32 [%0], %1, [%2];"
                :: "r"(peer_hbuf + off0), "r"(b0), "r"(peer_mbar + 16 + slot) : "memory");
            asm volatile(
                "st.async.shared::cluster.mbarrier::complete_tx::bytes.b32 [%0], %1, [%2];"
                :: "r"(peer_hbuf + off1), "r"(b1), "r"(peer_mbar + 16 + slot) : "memory");
        } else if (WRITE_SEQ) {
            hs[(size_t)(2 * cb + 0) * SEQ * WIDTH + (size_t)t * WIDTH + j] = h0n;
            hs[(size_t)(2 * cb + 1) * SEQ * WIDTH + (size_t)t * WIDTH + j] = h1n;
        }
    }

    // drain final step's stores
    {
        const uint32_t fslot = (uint32_t)(511 & 1) * 8;
        const uint32_t fpar  = (uint32_t)((511 >> 1) & 1);
        mbar_wait(mbar_u32 + fslot, fpar);
        mbar_wait(mbar_u32 + 16 + fslot, fpar);
    }

    if (FINAL && rank == 0) {
        #pragma unroll 1
        for (int r = 0; r < 2; r++) {
            const float h = hbuf[0][r][tid];   // final h (t=511 wrote phase 0)
            red[tid]         = h * Wd[tid * 2 + 0];
            red[WIDTH + tid] = h * Wd[tid * 2 + 1];
            __syncthreads();
            #pragma unroll
            for (int sft = 128; sft > 0; sft >>= 1) {
                if (tid < sft) {
                    red[tid]         += red[tid + sft];
                    red[WIDTH + tid] += red[WIDTH + tid + sft];
                }
                __syncthreads();
            }
            if (tid == 0) {
                const float l0 = red[0] + bd[0];
                const float l1 = red[WIDTH] + bd[1];
                const float mx = fmaxf(l0, l1);
                const float e0 = expf(l0 - mx);
                const float e1 = expf(l1 - mx);
                const float inv = 1.0f / (e0 + e1);
                out[(2 * cb + r) * 2 + 0] = e0 * inv;
                out[(2 * cb + r) * 2 + 1] = e1 * inv;
            }
            __syncthreads();
        }
    }

    asm volatile("barrier.cluster.arrive.aligned;" ::: "memory");
    asm volatile("barrier.cluster.wait.aligned;" ::: "memory");
}

// ============================================================================
// launcher
// ============================================================================
extern "C" void kernel_launch(void* const* d_in, const int* in_sizes, int n_in,
                              void* d_out, int out_size)
{
    const int*   tokens = (const int*)  d_in[0];
    const float* emb    = (const float*)d_in[1];
    const float* W1     = (const float*)d_in[2];
    const float* U1     = (const float*)d_in[3];
    const float* b1     = (const float*)d_in[4];
    const float* W2     = (const float*)d_in[5];
    const float* U2     = (const float*)d_in[6];
    const float* b2     = (const float*)d_in[7];
    const float* Wd     = (const float*)d_in[8];
    const float* bd     = (const float*)d_in[9];
    float* out = (float*)d_out;

    float* bufA; cudaGetSymbolAddress((void**)&bufA, g_bufA);
    float* bufB; cudaGetSymbolAddress((void**)&bufB, g_bufB);

    cudaFuncSetAttribute(gemm_kernel<true>,
                         cudaFuncAttributeMaxDynamicSharedMemorySize, (int)GEMM_SMEM);
    cudaFuncSetAttribute(gemm_kernel<false>,
                         cudaFuncAttributeMaxDynamicSharedMemorySize, (int)GEMM_SMEM);

    dim3 ggrid(ROWS / 128, WIDTH / 128);   // (256, 2)

    gemm_kernel<true><<<ggrid, 512, GEMM_SMEM>>>(tokens, emb, W1, b1, bufA, EMBED);
    // 32 clusters x 2 CTAs = 64 CTAs; each cluster scans 2 batch rows
    rnn_kernel<true, false><<<BATCH, 256>>>(bufA, U1, bufB,
                                            nullptr, nullptr, nullptr);
    gemm_kernel<false><<<ggrid, 512, GEMM_SMEM>>>(nullptr, bufB, W2, b2, bufA, WIDTH);
    rnn_kernel<false, true><<<BATCH, 256>>>(bufA, U2, nullptr,
                                            Wd, bd, out);

    (void)in_sizes; (void)n_in; (void)out_size;
}

// round 13
// speedup vs baseline: 1.4552x; 1.4552x over previous
#include <cuda_runtime.h>
#include <math.h>
#include <stdint.h>

typedef unsigned long long ull;

// ---------------------------------------------------------------- constants
constexpr int BATCH = 64;
constexpr int SEQ   = 512;
constexpr int WIDTH = 256;   // hidden width
constexpr int EMBED = 512;   // 2*WIDTH
constexpr int ROWS  = BATCH * SEQ;   // 32768 GEMM rows

// ---------------------------------------------------------------- scratch
__device__ float g_bufA[BATCH * SEQ * WIDTH];
__device__ float g_bufB[BATCH * SEQ * WIDTH];

// ---------------------------------------------------------------- f32x2 helpers
__device__ __forceinline__ ull pk2(float lo, float hi) {
    ull r; asm("mov.b64 %0,{%1,%2};" : "=l"(r) : "f"(lo), "f"(hi)); return r;
}
__device__ __forceinline__ void up2(ull v, float& lo, float& hi) {
    asm("mov.b64 {%0,%1},%2;" : "=f"(lo), "=f"(hi) : "l"(v));
}
__device__ __forceinline__ ull ffma2(ull a, ull b, ull c) {
    ull d; asm("fma.rn.f32x2 %0,%1,%2,%3;" : "=l"(d) : "l"(a), "l"(b), "l"(c)); return d;
}
__device__ __forceinline__ uint32_t smem_u32(const void* p) {
    uint32_t a;
    asm("{ .reg .u64 t; cvta.to.shared.u64 t, %1; cvt.u32.u64 %0, t; }"
        : "=r"(a) : "l"(p));
    return a;
}
__device__ __forceinline__ void mbar_wait(uint32_t mb, uint32_t parity) {
    uint32_t done;
    asm volatile(
        "{\n\t.reg .pred p;\n\t"
        "mbarrier.try_wait.parity.acquire.cta.shared::cta.b64 p, [%1], %2;\n\t"
        "selp.b32 %0, 1, 0, p;\n\t}"
        : "=r"(done) : "r"(mb), "r"(parity) : "memory");
    if (!done) {
        asm volatile(
            "{\n\t.reg .pred P1;\n\t"
            "WL_%=:\n\t"
            "mbarrier.try_wait.parity.acquire.cta.shared::cta.b64 P1, [%0], %1, 0x989680;\n\t"
            "@P1 bra.uni WD_%=;\n\t"
            "bra.uni WL_%=;\n\t"
            "WD_%=:\n\t}"
            :: "r"(mb), "r"(parity) : "memory");
    }
}

// ============================================================================
// GEMM: C[R, 256] = A[R, K] @ Wm[K, 256] + bias
// 128x128 CTA tile, 256 threads, 8x8 microtile, GK=32, DOUBLE-BUFFERED smem.
// A tile pre-duplicated (a,a) in smem; broadcast ulonglong2 reads.
// ============================================================================
constexpr int GK = 32;
constexpr int BS_STR = 132;                          // Bs row stride (floats)
constexpr int GBUF = GK * 128 * 8 + GK * BS_STR * 4; // 49664 B per buffer
constexpr size_t GEMM_SMEM = (size_t)2 * GBUF;       // ~97 KB

template<bool GATHER>
__global__ void __launch_bounds__(256, 1)
gemm_kernel(const int* __restrict__ tokens, const float* __restrict__ A,
            const float* __restrict__ Wm, const float* __restrict__ bias,
            float* __restrict__ C, int K)
{
    extern __shared__ unsigned char gsm[];

    const int tid = threadIdx.x;
    const int r0  = blockIdx.x * 128;
    const int n0  = blockIdx.y * 128;

    // --- A loader: 128 rows x 32 k; thread reads 16 k of one row (4 float4)
    const int lrow = tid >> 1;            // 0..127
    const int lk16 = (tid & 1) * 16;      // 0 or 16
    const float* arow;
    if (GATHER) arow = A + (size_t)tokens[r0 + lrow] * (size_t)K;
    else        arow = A + (size_t)(r0 + lrow) * (size_t)K;

    // --- B loader: 32 k x 128 n; thread reads 16 n of one k-row (4 float4)
    const int bk = tid >> 3;              // 0..31
    const int bn = (tid & 7) * 16;        // 0..112

    // --- compute mapping: 16x16 thread grid, 8x8 microtile
    const int ty = tid >> 4;              // 0..15
    const int tx = tid & 15;              // 0..15
    const int cm = ty * 8;
    const int cn = tx * 8;

    ull acc[8][4];
    #pragma unroll
    for (int r = 0; r < 8; r++)
        #pragma unroll
        for (int c = 0; c < 4; c++) acc[r][c] = 0ull;

    float4 av[4], bv4[4];
    #pragma unroll
    for (int q = 0; q < 4; q++) {
        av[q]  = *(const float4*)(arow + lk16 + q * 4);
        bv4[q] = *(const float4*)(Wm + (size_t)bk * WIDTH + n0 + bn + q * 4);
    }

    int cur = 0;
    // store initial tile into buffer 0
    {
        ull*   ATu = (ull*)(gsm + cur * GBUF);
        float* Bs  = (float*)(gsm + cur * GBUF + GK * 128 * 8);
        #pragma unroll
        for (int q = 0; q < 4; q++) {
            ATu[(lk16 + q * 4 + 0) * 128 + lrow] = pk2(av[q].x, av[q].x);
            ATu[(lk16 + q * 4 + 1) * 128 + lrow] = pk2(av[q].y, av[q].y);
            ATu[(lk16 + q * 4 + 2) * 128 + lrow] = pk2(av[q].z, av[q].z);
            ATu[(lk16 + q * 4 + 3) * 128 + lrow] = pk2(av[q].w, av[q].w);
            *(float4*)&Bs[bk * BS_STR + bn + q * 4] = bv4[q];
        }
    }
    __syncthreads();

    #pragma unroll 1
    for (int k0 = 0; k0 < K; k0 += GK) {
        const bool more = (k0 + GK < K);
        // prefetch next tile into registers (hidden by compute below)
        if (more) {
            #pragma unroll
            for (int q = 0; q < 4; q++) {
                av[q]  = *(const float4*)(arow + k0 + GK + lk16 + q * 4);
                bv4[q] = *(const float4*)(Wm + (size_t)(k0 + GK + bk) * WIDTH + n0 + bn + q * 4);
            }
        }

        const ull*   ATu = (const ull*)(gsm + cur * GBUF);
        const float* Bs  = (const float*)(gsm + cur * GBUF + GK * 128 * 8);

        #pragma unroll 8
        for (int kk = 0; kk < GK; kk++) {
            ulonglong2 bvA = *(const ulonglong2*)&Bs[kk * BS_STR + cn];
            ulonglong2 bvB = *(const ulonglong2*)&Bs[kk * BS_STR + cn + 4];
            const ull* arow_s = &ATu[kk * 128 + cm];
            ulonglong2 ad01 = *(const ulonglong2*)(arow_s + 0);
            ulonglong2 ad23 = *(const ulonglong2*)(arow_s + 2);
            ulonglong2 ad45 = *(const ulonglong2*)(arow_s + 4);
            ulonglong2 ad67 = *(const ulonglong2*)(arow_s + 6);
            ull ad[8] = { ad01.x, ad01.y, ad23.x, ad23.y,
                          ad45.x, ad45.y, ad67.x, ad67.y };
            #pragma unroll
            for (int r = 0; r < 8; r++) {
                acc[r][0] = ffma2(ad[r], bvA.x, acc[r][0]);
                acc[r][1] = ffma2(ad[r], bvA.y, acc[r][1]);
                acc[r][2] = ffma2(ad[r], bvB.x, acc[r][2]);
                acc[r][3] = ffma2(ad[r], bvB.y, acc[r][3]);
            }
        }

        // store prefetched tile into the other buffer
        if (more) {
            ull*   ATn = (ull*)(gsm + (cur ^ 1) * GBUF);
            float* Bsn = (float*)(gsm + (cur ^ 1) * GBUF + GK * 128 * 8);
            #pragma unroll
            for (int q = 0; q < 4; q++) {
                ATn[(lk16 + q * 4 + 0) * 128 + lrow] = pk2(av[q].x, av[q].x);
                ATn[(lk16 + q * 4 + 1) * 128 + lrow] = pk2(av[q].y, av[q].y);
                ATn[(lk16 + q * 4 + 2) * 128 + lrow] = pk2(av[q].z, av[q].z);
                ATn[(lk16 + q * 4 + 3) * 128 + lrow] = pk2(av[q].w, av[q].w);
                *(float4*)&Bsn[bk * BS_STR + bn + q * 4] = bv4[q];
            }
        }
        __syncthreads();
        cur ^= 1;
    }

    // epilogue: bias + store 8x8
    float bvals[8];
    #pragma unroll
    for (int c = 0; c < 8; c++) bvals[c] = bias[n0 + cn + c];
    #pragma unroll
    for (int r = 0; r < 8; r++) {
        float o[8];
        up2(acc[r][0], o[0], o[1]);
        up2(acc[r][1], o[2], o[3]);
        up2(acc[r][2], o[4], o[5]);
        up2(acc[r][3], o[6], o[7]);
        float4 w0 = make_float4(o[0] + bvals[0], o[1] + bvals[1],
                                o[2] + bvals[2], o[3] + bvals[3]);
        float4 w1 = make_float4(o[4] + bvals[4], o[5] + bvals[5],
                                o[6] + bvals[6], o[7] + bvals[7]);
        float* crow = &C[(size_t)(r0 + cm + r) * WIDTH + n0 + cn];
        *(float4*)(crow)     = w0;
        *(float4*)(crow + 4) = w1;
    }
}

// ============================================================================
// RNN scan, cluster-of-2 per batch row, st.async SPLIT-WAIT pipeline.
// (byte-identical to R9/R10 — validated 352us, rel_err 5.9e-7)
// ============================================================================
constexpr int HSTR = 264;    // floats per h buffer (256 + pad)

template<bool WRITE_SEQ, bool FINAL>
__global__ void __launch_bounds__(256, 1) __cluster_dims__(2, 1, 1)
rnn_kernel(const float* __restrict__ xw, const float* __restrict__ U,
           float* __restrict__ hs, const float* __restrict__ Wd,
           const float* __restrict__ bd, float* __restrict__ out)
{
    __shared__ __align__(16) float hbuf[2][HSTR];
    __shared__ __align__(8)  ull mbars[4];   // [0..1]=mbarL phases, [2..3]=mbarP phases
    __shared__ float red[2 * WIDTH];

    const int tid = threadIdx.x;
    uint32_t rank;
    asm("mov.u32 %0, %%cluster_ctarank;" : "=r"(rank));
    const int b    = blockIdx.x >> 1;
    const int half = tid & 1;
    const int jl   = tid >> 1;             // 0..127
    const int j    = (int)rank * 128 + jl; // global column

    const int kbL = (int)rank * 128 + half * 64;
    const int kbP = (int)(rank ^ 1u) * 128 + half * 64;

    ull uL[32], uP[32];
    #pragma unroll
    for (int m = 0; m < 32; m++) {
        uL[m] = pk2(U[(size_t)(kbL + 2 * m) * WIDTH + j],
                    U[(size_t)(kbL + 2 * m + 1) * WIDTH + j]);
        uP[m] = pk2(U[(size_t)(kbP + 2 * m) * WIDTH + j],
                    U[(size_t)(kbP + 2 * m + 1) * WIDTH + j]);
    }

    for (int i = tid; i < HSTR; i += 256) hbuf[0][i] = 0.0f;
    if (tid == 0) {
        #pragma unroll
        for (int i = 0; i < 4; i++)
            asm volatile("mbarrier.init.shared.b64 [%0], %1;"
                         :: "r"(smem_u32(&mbars[i])), "r"(1) : "memory");
    }
    __syncthreads();
    asm volatile("barrier.cluster.arrive.aligned;" ::: "memory");
    asm volatile("barrier.cluster.wait.aligned;" ::: "memory");

    const uint32_t hbuf_u32 = smem_u32(&hbuf[0][0]);
    const uint32_t mbar_u32 = smem_u32(&mbars[0]);
    uint32_t self_hbuf, self_mbar, peer_hbuf, peer_mbar;
    {
        uint32_t sr = rank, pr = rank ^ 1u;
        asm("mapa.shared::cluster.u32 %0, %1, %2;" : "=r"(self_hbuf) : "r"(hbuf_u32), "r"(sr));
        asm("mapa.shared::cluster.u32 %0, %1, %2;" : "=r"(self_mbar) : "r"(mbar_u32), "r"(sr));
        asm("mapa.shared::cluster.u32 %0, %1, %2;" : "=r"(peer_hbuf) : "r"(hbuf_u32), "r"(pr));
        asm("mapa.shared::cluster.u32 %0, %1, %2;" : "=r"(peer_mbar) : "r"(mbar_u32), "r"(pr));
    }

    const float* xb = xw + (size_t)b * SEQ * WIDTH + j;
    float xt_next = xb[0];

    #pragma unroll 1
    for (int t = 0; t < SEQ; t++) {
        const int rd = t & 1;
        const int wr = rd ^ 1;
        const uint32_t slot  = (uint32_t)(t & 1) * 8;
        const uint32_t pslot = (uint32_t)((t ^ 1) & 1) * 8;
        const uint32_t ppar  = (uint32_t)(((t - 1) >> 1) & 1);

        if (tid == 0) {
            asm volatile("mbarrier.arrive.expect_tx.shared.b64 _, [%0], %1;"
                         :: "r"(mbar_u32 + slot), "r"(512) : "memory");        // mbarL
            asm volatile("mbarrier.arrive.expect_tx.shared.b64 _, [%0], %1;"
                         :: "r"(mbar_u32 + 16 + slot), "r"(512) : "memory");   // mbarP
        }

        const float xt = xt_next;
        if (t + 1 < SEQ) xt_next = xb[(size_t)(t + 1) * WIDTH];

        ull a0 = 0ull, a1 = 0ull, a2 = 0ull, a3 = 0ull;

        if (t > 0) mbar_wait(mbar_u32 + pslot, ppar);          // mbarL[prev]
        {
            const ull* hp = (const ull*)&hbuf[rd][0] + (kbL >> 1);
            #pragma unroll
            for (int m = 0; m < 32; m += 4) {
                ulonglong2 h01 = *(const ulonglong2*)(hp + m);
                ulonglong2 h23 = *(const ulonglong2*)(hp + m + 2);
                a0 = ffma2(h01.x, uL[m + 0], a0);
                a1 = ffma2(h01.y, uL[m + 1], a1);
                a2 = ffma2(h23.x, uL[m + 2], a2);
                a3 = ffma2(h23.y, uL[m + 3], a3);
            }
        }

        if (t > 0) mbar_wait(mbar_u32 + 16 + pslot, ppar);     // mbarP[prev]
        {
            const ull* hp = (const ull*)&hbuf[rd][0] + (kbP >> 1);
            #pragma unroll
            for (int m = 0; m < 32; m += 4) {
                ulonglong2 h01 = *(const ulonglong2*)(hp + m);
                ulonglong2 h23 = *(const ulonglong2*)(hp + m + 2);
                a0 = ffma2(h01.x, uP[m + 0], a0);
                a1 = ffma2(h01.y, uP[m + 1], a1);
                a2 = ffma2(h23.x, uP[m + 2], a2);
                a3 = ffma2(h23.y, uP[m + 3], a3);
            }
        }

        float s0, s1, s2, s3, s4, s5, s6, s7;
        up2(a0, s0, s1); up2(a1, s2, s3); up2(a2, s4, s5); up2(a3, s6, s7);
        float s = (((s0 + s1) + (s2 + s3)) + ((s4 + s5) + (s6 + s7)));
        s += __shfl_xor_sync(0xFFFFFFFFu, s, 1);

        const float e  = __expf(2.0f * (xt + s));
        const float hn = 1.0f - __fdividef(2.0f, e + 1.0f);

        if (half == 0) {
            const uint32_t off = (uint32_t)(wr * HSTR * 4 + j * 4);
            const uint32_t hbits = __float_as_uint(hn);
            asm volatile(
                "st.async.shared::cluster.mbarrier::complete_tx::bytes.b32 [%0], %1, [%2];"
                :: "r"(self_hbuf + off), "r"(hbits), "r"(self_mbar + slot) : "memory");
            asm volatile(
                "st.async.shared::cluster.mbarrier::complete_tx::bytes.b32 [%0], %1, [%2];"
                :: "r"(peer_hbuf + off), "r"(hbits), "r"(peer_mbar + 16 + slot) : "memory");
        } else if (WRITE_SEQ) {
            hs[(size_t)b * SEQ * WIDTH + (size_t)t * WIDTH + j] = hn;
        }
    }

    {
        const uint32_t fslot = (uint32_t)(511 & 1) * 8;
        const uint32_t fpar  = (uint32_t)((511 >> 1) & 1);
        mbar_wait(mbar_u32 + fslot, fpar);
        mbar_wait(mbar_u32 + 16 + fslot, fpar);
    }

    if (FINAL && rank == 0) {
        const float h = hbuf[0][tid];
        red[tid]         = h * Wd[tid * 2 + 0];
        red[WIDTH + tid] = h * Wd[tid * 2 + 1];
        __syncthreads();
        #pragma unroll
        for (int sft = 128; sft > 0; sft >>= 1) {
            if (tid < sft) {
                red[tid]         += red[tid + sft];
                red[WIDTH + tid] += red[WIDTH + tid + sft];
            }
            __syncthreads();
        }
        if (tid == 0) {
            const float l0 = red[0] + bd[0];
            const float l1 = red[WIDTH] + bd[1];
            const float mx = fmaxf(l0, l1);
            const float e0 = expf(l0 - mx);
            const float e1 = expf(l1 - mx);
            const float inv = 1.0f / (e0 + e1);
            out[b * 2 + 0] = e0 * inv;
            out[b * 2 + 1] = e1 * inv;
        }
    }

    asm volatile("barrier.cluster.arrive.aligned;" ::: "memory");
    asm volatile("barrier.cluster.wait.aligned;" ::: "memory");
}

// ============================================================================
// launcher
// ============================================================================
extern "C" void kernel_launch(void* const* d_in, const int* in_sizes, int n_in,
                              void* d_out, int out_size)
{
    const int*   tokens = (const int*)  d_in[0];
    const float* emb    = (const float*)d_in[1];
    const float* W1     = (const float*)d_in[2];
    const float* U1     = (const float*)d_in[3];
    const float* b1     = (const float*)d_in[4];
    const float* W2     = (const float*)d_in[5];
    const float* U2     = (const float*)d_in[6];
    const float* b2     = (const float*)d_in[7];
    const float* Wd     = (const float*)d_in[8];
    const float* bd     = (const float*)d_in[9];
    float* out = (float*)d_out;

    float* bufA; cudaGetSymbolAddress((void**)&bufA, g_bufA);
    float* bufB; cudaGetSymbolAddress((void**)&bufB, g_bufB);

    cudaFuncSetAttribute(gemm_kernel<true>,
                         cudaFuncAttributeMaxDynamicSharedMemorySize, (int)GEMM_SMEM);
    cudaFuncSetAttribute(gemm_kernel<false>,
                         cudaFuncAttributeMaxDynamicSharedMemorySize, (int)GEMM_SMEM);

    dim3 ggrid(ROWS / 128, WIDTH / 128);   // (256, 2)

    gemm_kernel<true><<<ggrid, 256, GEMM_SMEM>>>(tokens, emb, W1, b1, bufA, EMBED);
    rnn_kernel<true, false><<<2 * BATCH, 256>>>(bufA, U1, bufB,
                                                nullptr, nullptr, nullptr);
    gemm_kernel<false><<<ggrid, 256, GEMM_SMEM>>>(nullptr, bufB, W2, b2, bufA, WIDTH);
    rnn_kernel<false, true><<<2 * BATCH, 256>>>(bufA, U2, nullptr,
                                                Wd, bd, out);

    (void)in_sizes; (void)n_in; (void)out_size;
}

// round 14
// speedup vs baseline: 1.4819x; 1.0184x over previous
#include <cuda_runtime.h>
#include <math.h>
#include <stdint.h>

typedef unsigned long long ull;

// ---------------------------------------------------------------- constants
constexpr int BATCH = 64;
constexpr int SEQ   = 512;
constexpr int WIDTH = 256;   // hidden width
constexpr int EMBED = 512;   // 2*WIDTH
constexpr int ROWS  = BATCH * SEQ;   // 32768 GEMM rows

// ---------------------------------------------------------------- scratch
__device__ float g_bufA[BATCH * SEQ * WIDTH];
__device__ float g_bufB[BATCH * SEQ * WIDTH];

// ---------------------------------------------------------------- f32x2 helpers
__device__ __forceinline__ ull pk2(float lo, float hi) {
    ull r; asm("mov.b64 %0,{%1,%2};" : "=l"(r) : "f"(lo), "f"(hi)); return r;
}
__device__ __forceinline__ void up2(ull v, float& lo, float& hi) {
    asm("mov.b64 {%0,%1},%2;" : "=f"(lo), "=f"(hi) : "l"(v));
}
__device__ __forceinline__ ull ffma2(ull a, ull b, ull c) {
    ull d; asm("fma.rn.f32x2 %0,%1,%2,%3;" : "=l"(d) : "l"(a), "l"(b), "l"(c)); return d;
}
__device__ __forceinline__ uint32_t smem_u32(const void* p) {
    uint32_t a;
    asm("{ .reg .u64 t; cvta.to.shared.u64 t, %1; cvt.u32.u64 %0, t; }"
        : "=r"(a) : "l"(p));
    return a;
}
__device__ __forceinline__ void mbar_wait(uint32_t mb, uint32_t parity) {
    uint32_t done;
    asm volatile(
        "{\n\t.reg .pred p;\n\t"
        "mbarrier.try_wait.parity.acquire.cta.shared::cta.b64 p, [%1], %2;\n\t"
        "selp.b32 %0, 1, 0, p;\n\t}"
        : "=r"(done) : "r"(mb), "r"(parity) : "memory");
    if (!done) {
        asm volatile(
            "{\n\t.reg .pred P1;\n\t"
            "WL_%=:\n\t"
            "mbarrier.try_wait.parity.acquire.cta.shared::cta.b64 P1, [%0], %1, 0x989680;\n\t"
            "@P1 bra.uni WD_%=;\n\t"
            "bra.uni WL_%=;\n\t"
            "WD_%=:\n\t}"
            :: "r"(mb), "r"(parity) : "memory");
    }
}

// ============================================================================
// GEMM: C[R, 256] = A[R, K] @ Wm[K, 256] + bias
// 128x128 CTA tile, 512 threads, GK=32, register prefetch. (R10, validated)
// ============================================================================
constexpr int GK = 32;
constexpr int BS_STR = 132;
constexpr size_t GEMM_SMEM = (size_t)GK * 128 * 8
                           + (size_t)GK * BS_STR * 4;

template<bool GATHER>
__global__ void __launch_bounds__(512, 1)
gemm_kernel(const int* __restrict__ tokens, const float* __restrict__ A,
            const float* __restrict__ Wm, const float* __restrict__ bias,
            float* __restrict__ C, int K)
{
    extern __shared__ unsigned char gsm[];
    ull*   ATu = (ull*)gsm;
    float* Bs  = (float*)(gsm + (size_t)GK * 128 * 8);

    const int tid = threadIdx.x;
    const int r0  = blockIdx.x * 128;
    const int n0  = blockIdx.y * 128;

    const int lrow = tid >> 2;
    const int lk8  = (tid & 3) * 8;
    const float* arow;
    if (GATHER) arow = A + (size_t)tokens[r0 + lrow] * (size_t)K;
    else        arow = A + (size_t)(r0 + lrow) * (size_t)K;

    const int bk = tid >> 4;
    const int bn = (tid & 15) * 8;

    const int ty = tid >> 5;
    const int tx = tid & 31;
    const int cm = ty * 8;
    const int cn = tx * 4;

    ull acc[8][2];
    #pragma unroll
    for (int r = 0; r < 8; r++) { acc[r][0] = 0ull; acc[r][1] = 0ull; }

    float4 a0v = *(const float4*)(arow + lk8);
    float4 a1v = *(const float4*)(arow + lk8 + 4);
    float4 b0v = *(const float4*)(Wm + (size_t)bk * WIDTH + n0 + bn);
    float4 b1v = *(const float4*)(Wm + (size_t)bk * WIDTH + n0 + bn + 4);

    #pragma unroll 1
    for (int k0 = 0; k0 < K; k0 += GK) {
        __syncthreads();
        ATu[(lk8 + 0) * 128 + lrow] = pk2(a0v.x, a0v.x);
        ATu[(lk8 + 1) * 128 + lrow] = pk2(a0v.y, a0v.y);
        ATu[(lk8 + 2) * 128 + lrow] = pk2(a0v.z, a0v.z);
        ATu[(lk8 + 3) * 128 + lrow] = pk2(a0v.w, a0v.w);
        ATu[(lk8 + 4) * 128 + lrow] = pk2(a1v.x, a1v.x);
        ATu[(lk8 + 5) * 128 + lrow] = pk2(a1v.y, a1v.y);
        ATu[(lk8 + 6) * 128 + lrow] = pk2(a1v.z, a1v.z);
        ATu[(lk8 + 7) * 128 + lrow] = pk2(a1v.w, a1v.w);
        *(float4*)&Bs[bk * BS_STR + bn]     = b0v;
        *(float4*)&Bs[bk * BS_STR + bn + 4] = b1v;
        __syncthreads();

        if (k0 + GK < K) {
            a0v = *(const float4*)(arow + k0 + GK + lk8);
            a1v = *(const float4*)(arow + k0 + GK + lk8 + 4);
            b0v = *(const float4*)(Wm + (size_t)(k0 + GK + bk) * WIDTH + n0 + bn);
            b1v = *(const float4*)(Wm + (size_t)(k0 + GK + bk) * WIDTH + n0 + bn + 4);
        }

        #pragma unroll
        for (int kk = 0; kk < GK; kk++) {
            ulonglong2 bv = *(const ulonglong2*)&Bs[kk * BS_STR + cn];
            const ull* arow_s = &ATu[kk * 128 + cm];
            ulonglong2 ad01 = *(const ulonglong2*)(arow_s + 0);
            ulonglong2 ad23 = *(const ulonglong2*)(arow_s + 2);
            ulonglong2 ad45 = *(const ulonglong2*)(arow_s + 4);
            ulonglong2 ad67 = *(const ulonglong2*)(arow_s + 6);
            acc[0][0] = ffma2(ad01.x, bv.x, acc[0][0]);
            acc[0][1] = ffma2(ad01.x, bv.y, acc[0][1]);
            acc[1][0] = ffma2(ad01.y, bv.x, acc[1][0]);
            acc[1][1] = ffma2(ad01.y, bv.y, acc[1][1]);
            acc[2][0] = ffma2(ad23.x, bv.x, acc[2][0]);
            acc[2][1] = ffma2(ad23.x, bv.y, acc[2][1]);
            acc[3][0] = ffma2(ad23.y, bv.x, acc[3][0]);
            acc[3][1] = ffma2(ad23.y, bv.y, acc[3][1]);
            acc[4][0] = ffma2(ad45.x, bv.x, acc[4][0]);
            acc[4][1] = ffma2(ad45.x, bv.y, acc[4][1]);
            acc[5][0] = ffma2(ad45.y, bv.x, acc[5][0]);
            acc[5][1] = ffma2(ad45.y, bv.y, acc[5][1]);
            acc[6][0] = ffma2(ad67.x, bv.x, acc[6][0]);
            acc[6][1] = ffma2(ad67.x, bv.y, acc[6][1]);
            acc[7][0] = ffma2(ad67.y, bv.x, acc[7][0]);
            acc[7][1] = ffma2(ad67.y, bv.y, acc[7][1]);
        }
    }

    const float bv0 = bias[n0 + cn + 0];
    const float bv1 = bias[n0 + cn + 1];
    const float bv2 = bias[n0 + cn + 2];
    const float bv3 = bias[n0 + cn + 3];
    #pragma unroll
    for (int r = 0; r < 8; r++) {
        float c0, c1, c2, c3;
        up2(acc[r][0], c0, c1);
        up2(acc[r][1], c2, c3);
        float4 o = make_float4(c0 + bv0, c1 + bv1, c2 + bv2, c3 + bv3);
        *(float4*)&C[(size_t)(r0 + cm + r) * WIDTH + n0 + cn] = o;
    }
}

// ============================================================================
// RNN scan, cluster-of-2 per batch row, st.async SPLIT-WAIT pipeline.
// R9 structure; changes: half1 issues the remote st.async (earlier DSMEM
// departure, parallel with half0's self store), time loop unrolled x2.
// ============================================================================
constexpr int HSTR = 264;    // floats per h buffer (256 + pad)

template<bool WRITE_SEQ, bool FINAL>
__global__ void __launch_bounds__(256, 1) __cluster_dims__(2, 1, 1)
rnn_kernel(const float* __restrict__ xw, const float* __restrict__ U,
           float* __restrict__ hs, const float* __restrict__ Wd,
           const float* __restrict__ bd, float* __restrict__ out)
{
    __shared__ __align__(16) float hbuf[2][HSTR];
    __shared__ __align__(8)  ull mbars[4];   // [0..1]=mbarL phases, [2..3]=mbarP phases
    __shared__ float red[2 * WIDTH];

    const int tid = threadIdx.x;
    uint32_t rank;
    asm("mov.u32 %0, %%cluster_ctarank;" : "=r"(rank));
    const int b    = blockIdx.x >> 1;
    const int half = tid & 1;
    const int jl   = tid >> 1;             // 0..127
    const int j    = (int)rank * 128 + jl; // global column

    const int kbL = (int)rank * 128 + half * 64;
    const int kbP = (int)(rank ^ 1u) * 128 + half * 64;

    ull uL[32], uP[32];
    #pragma unroll
    for (int m = 0; m < 32; m++) {
        uL[m] = pk2(U[(size_t)(kbL + 2 * m) * WIDTH + j],
                    U[(size_t)(kbL + 2 * m + 1) * WIDTH + j]);
        uP[m] = pk2(U[(size_t)(kbP + 2 * m) * WIDTH + j],
                    U[(size_t)(kbP + 2 * m + 1) * WIDTH + j]);
    }

    for (int i = tid; i < HSTR; i += 256) hbuf[0][i] = 0.0f;
    if (tid == 0) {
        #pragma unroll
        for (int i = 0; i < 4; i++)
            asm volatile("mbarrier.init.shared.b64 [%0], %1;"
                         :: "r"(smem_u32(&mbars[i])), "r"(1) : "memory");
    }
    __syncthreads();
    asm volatile("barrier.cluster.arrive.aligned;" ::: "memory");
    asm volatile("barrier.cluster.wait.aligned;" ::: "memory");

    const uint32_t hbuf_u32 = smem_u32(&hbuf[0][0]);
    const uint32_t mbar_u32 = smem_u32(&mbars[0]);
    uint32_t self_hbuf, self_mbar, peer_hbuf, peer_mbar;
    {
        uint32_t sr = rank, pr = rank ^ 1u;
        asm("mapa.shared::cluster.u32 %0, %1, %2;" : "=r"(self_hbuf) : "r"(hbuf_u32), "r"(sr));
        asm("mapa.shared::cluster.u32 %0, %1, %2;" : "=r"(self_mbar) : "r"(mbar_u32), "r"(sr));
        asm("mapa.shared::cluster.u32 %0, %1, %2;" : "=r"(peer_hbuf) : "r"(hbuf_u32), "r"(pr));
        asm("mapa.shared::cluster.u32 %0, %1, %2;" : "=r"(peer_mbar) : "r"(mbar_u32), "r"(pr));
    }

    const float* xb = xw + (size_t)b * SEQ * WIDTH + j;
    float xt_next = xb[0];

    #pragma unroll 2
    for (int t = 0; t < SEQ; t++) {
        const int rd = t & 1;
        const int wr = rd ^ 1;
        const uint32_t slot  = (uint32_t)(t & 1) * 8;
        const uint32_t pslot = (uint32_t)((t ^ 1) & 1) * 8;
        const uint32_t ppar  = (uint32_t)(((t - 1) >> 1) & 1);

        if (tid == 0) {
            asm volatile("mbarrier.arrive.expect_tx.shared.b64 _, [%0], %1;"
                         :: "r"(mbar_u32 + slot), "r"(512) : "memory");        // mbarL
            asm volatile("mbarrier.arrive.expect_tx.shared.b64 _, [%0], %1;"
                         :: "r"(mbar_u32 + 16 + slot), "r"(512) : "memory");   // mbarP
        }

        const float xt = xt_next;
        if (t + 1 < SEQ) xt_next = xb[(size_t)(t + 1) * WIDTH];

        ull a0 = 0ull, a1 = 0ull, a2 = 0ull, a3 = 0ull;

        if (t > 0) mbar_wait(mbar_u32 + pslot, ppar);          // mbarL[prev]
        {
            const ull* hp = (const ull*)&hbuf[rd][0] + (kbL >> 1);
            #pragma unroll
            for (int m = 0; m < 32; m += 4) {
                ulonglong2 h01 = *(const ulonglong2*)(hp + m);
                ulonglong2 h23 = *(const ulonglong2*)(hp + m + 2);
                a0 = ffma2(h01.x, uL[m + 0], a0);
                a1 = ffma2(h01.y, uL[m + 1], a1);
                a2 = ffma2(h23.x, uL[m + 2], a2);
                a3 = ffma2(h23.y, uL[m + 3], a3);
            }
        }

        if (t > 0) mbar_wait(mbar_u32 + 16 + pslot, ppar);     // mbarP[prev]
        {
            const ull* hp = (const ull*)&hbuf[rd][0] + (kbP >> 1);
            #pragma unroll
            for (int m = 0; m < 32; m += 4) {
                ulonglong2 h01 = *(const ulonglong2*)(hp + m);
                ulonglong2 h23 = *(const ulonglong2*)(hp + m + 2);
                a0 = ffma2(h01.x, uP[m + 0], a0);
                a1 = ffma2(h01.y, uP[m + 1], a1);
                a2 = ffma2(h23.x, uP[m + 2], a2);
                a3 = ffma2(h23.y, uP[m + 3], a3);
            }
        }

        float s0, s1, s2, s3, s4, s5, s6, s7;
        up2(a0, s0, s1); up2(a1, s2, s3); up2(a2, s4, s5); up2(a3, s6, s7);
        float s = (((s0 + s1) + (s2 + s3)) + ((s4 + s5) + (s6 + s7)));
        s += __shfl_xor_sync(0xFFFFFFFFu, s, 1);

        const float e  = __expf(2.0f * (xt + s));
        const float hn = 1.0f - __fdividef(2.0f, e + 1.0f);
        const uint32_t hbits = __float_as_uint(hn);
        const uint32_t off = (uint32_t)(wr * HSTR * 4 + j * 4);

        if (half == 1) {
            // remote store leaves first (longest flight), from lane 1
            asm volatile(
                "st.async.shared::cluster.mbarrier::complete_tx::bytes.b32 [%0], %1, [%2];"
                :: "r"(peer_hbuf + off), "r"(hbits), "r"(peer_mbar + 16 + slot) : "memory");
        } else {
            // self store + sequence output from lane 0 (same hn bits)
            asm volatile(
                "st.async.shared::cluster.mbarrier::complete_tx::bytes.b32 [%0], %1, [%2];"
                :: "r"(self_hbuf + off), "r"(hbits), "r"(self_mbar + slot) : "memory");
            if (WRITE_SEQ)
                hs[(size_t)b * SEQ * WIDTH + (size_t)t * WIDTH + j] = hn;
        }
    }

    {
        const uint32_t fslot = (uint32_t)(511 & 1) * 8;
        const uint32_t fpar  = (uint32_t)((511 >> 1) & 1);
        mbar_wait(mbar_u32 + fslot, fpar);
        mbar_wait(mbar_u32 + 16 + fslot, fpar);
    }

    if (FINAL && rank == 0) {
        const float h = hbuf[0][tid];
        red[tid]         = h * Wd[tid * 2 + 0];
        red[WIDTH + tid] = h * Wd[tid * 2 + 1];
        __syncthreads();
        #pragma unroll
        for (int sft = 128; sft > 0; sft >>= 1) {
            if (tid < sft) {
                red[tid]         += red[tid + sft];
                red[WIDTH + tid] += red[WIDTH + tid + sft];
            }
            __syncthreads();
        }
        if (tid == 0) {
            const float l0 = red[0] + bd[0];
            const float l1 = red[WIDTH] + bd[1];
            const float mx = fmaxf(l0, l1);
            const float e0 = expf(l0 - mx);
            const float e1 = expf(l1 - mx);
            const float inv = 1.0f / (e0 + e1);
            out[b * 2 + 0] = e0 * inv;
            out[b * 2 + 1] = e1 * inv;
        }
    }

    asm volatile("barrier.cluster.arrive.aligned;" ::: "memory");
    asm volatile("barrier.cluster.wait.aligned;" ::: "memory");
}

// ============================================================================
// launcher
// ============================================================================
extern "C" void kernel_launch(void* const* d_in, const int* in_sizes, int n_in,
                              void* d_out, int out_size)
{
    const int*   tokens = (const int*)  d_in[0];
    const float* emb    = (const float*)d_in[1];
    const float* W1     = (const float*)d_in[2];
    const float* U1     = (const float*)d_in[3];
    const float* b1     = (const float*)d_in[4];
    const float* W2     = (const float*)d_in[5];
    const float* U2     = (const float*)d_in[6];
    const float* b2     = (const float*)d_in[7];
    const float* Wd     = (const float*)d_in[8];
    const float* bd     = (const float*)d_in[9];
    float* out = (float*)d_out;

    float* bufA; cudaGetSymbolAddress((void**)&bufA, g_bufA);
    float* bufB; cudaGetSymbolAddress((void**)&bufB, g_bufB);

    cudaFuncSetAttribute(gemm_kernel<true>,
                         cudaFuncAttributeMaxDynamicSharedMemorySize, (int)GEMM_SMEM);
    cudaFuncSetAttribute(gemm_kernel<false>,
                         cudaFuncAttributeMaxDynamicSharedMemorySize, (int)GEMM_SMEM);

    dim3 ggrid(ROWS / 128, WIDTH / 128);   // (256, 2)

    gemm_kernel<true><<<ggrid, 512, GEMM_SMEM>>>(tokens, emb, W1, b1, bufA, EMBED);
    rnn_kernel<true, false><<<2 * BATCH, 256>>>(bufA, U1, bufB,
                                                nullptr, nullptr, nullptr);
    gemm_kernel<false><<<ggrid, 512, GEMM_SMEM>>>(nullptr, bufB, W2, b2, bufA, WIDTH);
    rnn_kernel<false, true><<<2 * BATCH, 256>>>(bufA, U2, nullptr,
                                                Wd, bd, out);

    (void)in_sizes; (void)n_in; (void)out_size;
}

// round 15
// speedup vs baseline: 1.5471x; 1.0440x over previous
#include <cuda_runtime.h>
#include <math.h>
#include <stdint.h>

typedef unsigned long long ull;

// ---------------------------------------------------------------- constants
constexpr int BATCH = 64;
constexpr int SEQ   = 512;
constexpr int WIDTH = 256;   // hidden width
constexpr int EMBED = 512;   // 2*WIDTH
constexpr int ROWS  = BATCH * SEQ;   // 32768 GEMM rows

// ---------------------------------------------------------------- scratch
__device__ float g_bufA[BATCH * SEQ * WIDTH];
__device__ float g_bufB[BATCH * SEQ * WIDTH];

// ---------------------------------------------------------------- f32x2 helpers
__device__ __forceinline__ ull pk2(float lo, float hi) {
    ull r; asm("mov.b64 %0,{%1,%2};" : "=l"(r) : "f"(lo), "f"(hi)); return r;
}
__device__ __forceinline__ void up2(ull v, float& lo, float& hi) {
    asm("mov.b64 {%0,%1},%2;" : "=f"(lo), "=f"(hi) : "l"(v));
}
__device__ __forceinline__ ull ffma2(ull a, ull b, ull c) {
    ull d; asm("fma.rn.f32x2 %0,%1,%2,%3;" : "=l"(d) : "l"(a), "l"(b), "l"(c)); return d;
}
__device__ __forceinline__ uint32_t smem_u32(const void* p) {
    uint32_t a;
    asm("{ .reg .u64 t; cvta.to.shared.u64 t, %1; cvt.u32.u64 %0, t; }"
        : "=r"(a) : "l"(p));
    return a;
}
__device__ __forceinline__ void mbar_wait(uint32_t mb, uint32_t parity) {
    uint32_t done;
    asm volatile(
        "{\n\t.reg .pred p;\n\t"
        "mbarrier.try_wait.parity.acquire.cta.shared::cta.b64 p, [%1], %2;\n\t"
        "selp.b32 %0, 1, 0, p;\n\t}"
        : "=r"(done) : "r"(mb), "r"(parity) : "memory");
    if (!done) {
        asm volatile(
            "{\n\t.reg .pred P1;\n\t"
            "WL_%=:\n\t"
            "mbarrier.try_wait.parity.acquire.cta.shared::cta.b64 P1, [%0], %1, 0x989680;\n\t"
            "@P1 bra.uni WD_%=;\n\t"
            "bra.uni WL_%=;\n\t"
            "WD_%=:\n\t}"
            :: "r"(mb), "r"(parity) : "memory");
    }
}

// ============================================================================
// GEMM: C[R, 256] = A[R, K] @ Wm[K, 256] + bias
// 128x128 CTA tile, 512 threads, GK=32, register prefetch. (R10, validated)
// ============================================================================
constexpr int GK = 32;
constexpr int BS_STR = 132;
constexpr size_t GEMM_SMEM = (size_t)GK * 128 * 8
                           + (size_t)GK * BS_STR * 4;

template<bool GATHER>
__global__ void __launch_bounds__(512, 1)
gemm_kernel(const int* __restrict__ tokens, const float* __restrict__ A,
            const float* __restrict__ Wm, const float* __restrict__ bias,
            float* __restrict__ C, int K)
{
    extern __shared__ unsigned char gsm[];
    ull*   ATu = (ull*)gsm;
    float* Bs  = (float*)(gsm + (size_t)GK * 128 * 8);

    const int tid = threadIdx.x;
    const int r0  = blockIdx.x * 128;
    const int n0  = blockIdx.y * 128;

    const int lrow = tid >> 2;
    const int lk8  = (tid & 3) * 8;
    const float* arow;
    if (GATHER) arow = A + (size_t)tokens[r0 + lrow] * (size_t)K;
    else        arow = A + (size_t)(r0 + lrow) * (size_t)K;

    const int bk = tid >> 4;
    const int bn = (tid & 15) * 8;

    const int ty = tid >> 5;
    const int tx = tid & 31;
    const int cm = ty * 8;
    const int cn = tx * 4;

    ull acc[8][2];
    #pragma unroll
    for (int r = 0; r < 8; r++) { acc[r][0] = 0ull; acc[r][1] = 0ull; }

    float4 a0v = *(const float4*)(arow + lk8);
    float4 a1v = *(const float4*)(arow + lk8 + 4);
    float4 b0v = *(const float4*)(Wm + (size_t)bk * WIDTH + n0 + bn);
    float4 b1v = *(const float4*)(Wm + (size_t)bk * WIDTH + n0 + bn + 4);

    #pragma unroll 1
    for (int k0 = 0; k0 < K; k0 += GK) {
        __syncthreads();
        ATu[(lk8 + 0) * 128 + lrow] = pk2(a0v.x, a0v.x);
        ATu[(lk8 + 1) * 128 + lrow] = pk2(a0v.y, a0v.y);
        ATu[(lk8 + 2) * 128 + lrow] = pk2(a0v.z, a0v.z);
        ATu[(lk8 + 3) * 128 + lrow] = pk2(a0v.w, a0v.w);
        ATu[(lk8 + 4) * 128 + lrow] = pk2(a1v.x, a1v.x);
        ATu[(lk8 + 5) * 128 + lrow] = pk2(a1v.y, a1v.y);
        ATu[(lk8 + 6) * 128 + lrow] = pk2(a1v.z, a1v.z);
        ATu[(lk8 + 7) * 128 + lrow] = pk2(a1v.w, a1v.w);
        *(float4*)&Bs[bk * BS_STR + bn]     = b0v;
        *(float4*)&Bs[bk * BS_STR + bn + 4] = b1v;
        __syncthreads();

        if (k0 + GK < K) {
            a0v = *(const float4*)(arow + k0 + GK + lk8);
            a1v = *(const float4*)(arow + k0 + GK + lk8 + 4);
            b0v = *(const float4*)(Wm + (size_t)(k0 + GK + bk) * WIDTH + n0 + bn);
            b1v = *(const float4*)(Wm + (size_t)(k0 + GK + bk) * WIDTH + n0 + bn + 4);
        }

        #pragma unroll
        for (int kk = 0; kk < GK; kk++) {
            ulonglong2 bv = *(const ulonglong2*)&Bs[kk * BS_STR + cn];
            const ull* arow_s = &ATu[kk * 128 + cm];
            ulonglong2 ad01 = *(const ulonglong2*)(arow_s + 0);
            ulonglong2 ad23 = *(const ulonglong2*)(arow_s + 2);
            ulonglong2 ad45 = *(const ulonglong2*)(arow_s + 4);
            ulonglong2 ad67 = *(const ulonglong2*)(arow_s + 6);
            acc[0][0] = ffma2(ad01.x, bv.x, acc[0][0]);
            acc[0][1] = ffma2(ad01.x, bv.y, acc[0][1]);
            acc[1][0] = ffma2(ad01.y, bv.x, acc[1][0]);
            acc[1][1] = ffma2(ad01.y, bv.y, acc[1][1]);
            acc[2][0] = ffma2(ad23.x, bv.x, acc[2][0]);
            acc[2][1] = ffma2(ad23.x, bv.y, acc[2][1]);
            acc[3][0] = ffma2(ad23.y, bv.x, acc[3][0]);
            acc[3][1] = ffma2(ad23.y, bv.y, acc[3][1]);
            acc[4][0] = ffma2(ad45.x, bv.x, acc[4][0]);
            acc[4][1] = ffma2(ad45.x, bv.y, acc[4][1]);
            acc[5][0] = ffma2(ad45.y, bv.x, acc[5][0]);
            acc[5][1] = ffma2(ad45.y, bv.y, acc[5][1]);
            acc[6][0] = ffma2(ad67.x, bv.x, acc[6][0]);
            acc[6][1] = ffma2(ad67.x, bv.y, acc[6][1]);
            acc[7][0] = ffma2(ad67.y, bv.x, acc[7][0]);
            acc[7][1] = ffma2(ad67.y, bv.y, acc[7][1]);
        }
    }

    const float bv0 = bias[n0 + cn + 0];
    const float bv1 = bias[n0 + cn + 1];
    const float bv2 = bias[n0 + cn + 2];
    const float bv3 = bias[n0 + cn + 3];
    #pragma unroll
    for (int r = 0; r < 8; r++) {
        float c0, c1, c2, c3;
        up2(acc[r][0], c0, c1);
        up2(acc[r][1], c2, c3);
        float4 o = make_float4(c0 + bv0, c1 + bv1, c2 + bv2, c3 + bv3);
        *(float4*)&C[(size_t)(r0 + cm + r) * WIDTH + n0 + cn] = o;
    }
}

// ============================================================================
// RNN scan, cluster-of-2 per batch row.
//  - rank owns output columns [rank*128, rank*128+128)
//  - 256 threads: column j = rank*128 + (tid>>1), k-half = tid&1
//  - 64 U pairs/thread in registers, split local-range / peer-range
//  - LOCAL half: plain STS + one __syncthreads per step (no mbar, no wait)
//  - PEER half: st.async -> peer's mbarP (512B tx), split-wait overlap
// ============================================================================
constexpr int HSTR = 264;    // floats per h buffer (256 + pad)

template<bool WRITE_SEQ, bool FINAL>
__global__ void __launch_bounds__(256, 1) __cluster_dims__(2, 1, 1)
rnn_kernel(const float* __restrict__ xw, const float* __restrict__ U,
           float* __restrict__ hs, const float* __restrict__ Wd,
           const float* __restrict__ bd, float* __restrict__ out)
{
    __shared__ __align__(16) float hbuf[2][HSTR];
    __shared__ __align__(8)  ull mbars[2];   // mbarP phase 0/1
    __shared__ float red[2 * WIDTH];

    const int tid = threadIdx.x;
    uint32_t rank;
    asm("mov.u32 %0, %%cluster_ctarank;" : "=r"(rank));
    const int b    = blockIdx.x >> 1;
    const int half = tid & 1;
    const int jl   = tid >> 1;             // 0..127
    const int j    = (int)rank * 128 + jl; // global column

    const int kbL = (int)rank * 128 + half * 64;        // locally-produced range
    const int kbP = (int)(rank ^ 1u) * 128 + half * 64; // peer-produced range

    ull uL[32], uP[32];
    #pragma unroll
    for (int m = 0; m < 32; m++) {
        uL[m] = pk2(U[(size_t)(kbL + 2 * m) * WIDTH + j],
                    U[(size_t)(kbL + 2 * m + 1) * WIDTH + j]);
        uP[m] = pk2(U[(size_t)(kbP + 2 * m) * WIDTH + j],
                    U[(size_t)(kbP + 2 * m + 1) * WIDTH + j]);
    }

    for (int i = tid; i < HSTR; i += 256) hbuf[0][i] = 0.0f;
    if (tid == 0) {
        asm volatile("mbarrier.init.shared.b64 [%0], %1;"
                     :: "r"(smem_u32(&mbars[0])), "r"(1) : "memory");
        asm volatile("mbarrier.init.shared.b64 [%0], %1;"
                     :: "r"(smem_u32(&mbars[1])), "r"(1) : "memory");
    }
    __syncthreads();
    asm volatile("barrier.cluster.arrive.aligned;" ::: "memory");
    asm volatile("barrier.cluster.wait.aligned;" ::: "memory");

    const uint32_t hbuf_u32 = smem_u32(&hbuf[0][0]);
    const uint32_t mbar_u32 = smem_u32(&mbars[0]);
    uint32_t peer_hbuf, peer_mbar;
    {
        uint32_t pr = rank ^ 1u;
        asm("mapa.shared::cluster.u32 %0, %1, %2;" : "=r"(peer_hbuf) : "r"(hbuf_u32), "r"(pr));
        asm("mapa.shared::cluster.u32 %0, %1, %2;" : "=r"(peer_mbar) : "r"(mbar_u32), "r"(pr));
    }

    const float* xb = xw + (size_t)b * SEQ * WIDTH + j;
    float xt_next = xb[0];

    #pragma unroll 1
    for (int t = 0; t < SEQ; t++) {
        const int rd = t & 1;
        const int wr = rd ^ 1;
        const uint32_t slot  = (uint32_t)(t & 1) * 8;
        const uint32_t pslot = (uint32_t)((t ^ 1) & 1) * 8;
        const uint32_t ppar  = (uint32_t)(((t - 1) >> 1) & 1);

        // arm this step's peer mbar (1 arrive + 512 expected bytes)
        if (tid == 0) {
            asm volatile("mbarrier.arrive.expect_tx.shared.b64 _, [%0], %1;"
                         :: "r"(mbar_u32 + slot), "r"(512) : "memory");
        }

        const float xt = xt_next;
        if (t + 1 < SEQ) xt_next = xb[(size_t)(t + 1) * WIDTH];

        ull a0 = 0ull, a1 = 0ull, a2 = 0ull, a3 = 0ull;

        // ---- phase 1: local-range pairs — NO WAIT (bar.sync at end of prev
        // step already published this CTA's STS h values)
        {
            const ull* hp = (const ull*)&hbuf[rd][0] + (kbL >> 1);
            #pragma unroll
            for (int m = 0; m < 32; m += 4) {
                ulonglong2 h01 = *(const ulonglong2*)(hp + m);
                ulonglong2 h23 = *(const ulonglong2*)(hp + m + 2);
                a0 = ffma2(h01.x, uL[m + 0], a0);
                a1 = ffma2(h01.y, uL[m + 1], a1);
                a2 = ffma2(h23.x, uL[m + 2], a2);
                a3 = ffma2(h23.y, uL[m + 3], a3);
            }
        }

        // ---- phase 2: peer-range pairs (DSMEM flight overlapped by phase 1)
        if (t > 0) mbar_wait(mbar_u32 + pslot, ppar);
        {
            const ull* hp = (const ull*)&hbuf[rd][0] + (kbP >> 1);
            #pragma unroll
            for (int m = 0; m < 32; m += 4) {
                ulonglong2 h01 = *(const ulonglong2*)(hp + m);
                ulonglong2 h23 = *(const ulonglong2*)(hp + m + 2);
                a0 = ffma2(h01.x, uP[m + 0], a0);
                a1 = ffma2(h01.y, uP[m + 1], a1);
                a2 = ffma2(h23.x, uP[m + 2], a2);
                a3 = ffma2(h23.y, uP[m + 3], a3);
            }
        }

        float s0, s1, s2, s3, s4, s5, s6, s7;
        up2(a0, s0, s1); up2(a1, s2, s3); up2(a2, s4, s5); up2(a3, s6, s7);
        float s = (((s0 + s1) + (s2 + s3)) + ((s4 + s5) + (s6 + s7)));
        s += __shfl_xor_sync(0xFFFFFFFFu, s, 1);   // combine k-halves

        const float e  = __expf(2.0f * (xt + s));
        const float hn = 1.0f - __fdividef(2.0f, e + 1.0f);

        if (half == 0) {
            // remote copy first (longest flight), then local STS
            const uint32_t off = (uint32_t)(wr * HSTR * 4 + j * 4);
            asm volatile(
                "st.async.shared::cluster.mbarrier::complete_tx::bytes.b32 [%0], %1, [%2];"
                :: "r"(peer_hbuf + off), "r"(__float_as_uint(hn)),
                   "r"(peer_mbar + slot) : "memory");
            hbuf[wr][j] = hn;                       // plain STS, local visibility
            if (WRITE_SEQ)
                hs[(size_t)b * SEQ * WIDTH + (size_t)t * WIDTH + j] = hn;
        }
        __syncthreads();   // publishes local STS; drains pending STS natively
    }

    // drain the final step's peer stores
    {
        const uint32_t fslot = (uint32_t)(511 & 1) * 8;
        const uint32_t fpar  = (uint32_t)((511 >> 1) & 1);
        mbar_wait(mbar_u32 + fslot, fpar);
    }

    if (FINAL && rank == 0) {
        const float h = hbuf[0][tid];   // t=511 wrote buffer 0
        red[tid]         = h * Wd[tid * 2 + 0];
        red[WIDTH + tid] = h * Wd[tid * 2 + 1];
        __syncthreads();
        #pragma unroll
        for (int sft = 128; sft > 0; sft >>= 1) {
            if (tid < sft) {
                red[tid]         += red[tid + sft];
                red[WIDTH + tid] += red[WIDTH + tid + sft];
            }
            __syncthreads();
        }
        if (tid == 0) {
            const float l0 = red[0] + bd[0];
            const float l1 = red[WIDTH] + bd[1];
            const float mx = fmaxf(l0, l1);
            const float e0 = expf(l0 - mx);
            const float e1 = expf(l1 - mx);
            const float inv = 1.0f / (e0 + e1);
            out[b * 2 + 0] = e0 * inv;
            out[b * 2 + 1] = e1 * inv;
        }
    }

    // no CTA exits while peer st.async traffic into its smem may be in flight
    asm volatile("barrier.cluster.arrive.aligned;" ::: "memory");
    asm volatile("barrier.cluster.wait.aligned;" ::: "memory");
}

// ============================================================================
// launcher
// ============================================================================
extern "C" void kernel_launch(void* const* d_in, const int* in_sizes, int n_in,
                              void* d_out, int out_size)
{
    const int*   tokens = (const int*)  d_in[0];
    const float* emb    = (const float*)d_in[1];
    const float* W1     = (const float*)d_in[2];
    const float* U1     = (const float*)d_in[3];
    const float* b1     = (const float*)d_in[4];
    const float* W2     = (const float*)d_in[5];
    const float* U2     = (const float*)d_in[6];
    const float* b2     = (const float*)d_in[7];
    const float* Wd     = (const float*)d_in[8];
    const float* bd     = (const float*)d_in[9];
    float* out = (float*)d_out;

    float* bufA; cudaGetSymbolAddress((void**)&bufA, g_bufA);
    float* bufB; cudaGetSymbolAddress((void**)&bufB, g_bufB);

    cudaFuncSetAttribute(gemm_kernel<true>,
                         cudaFuncAttributeMaxDynamicSharedMemorySize, (int)GEMM_SMEM);
    cudaFuncSetAttribute(gemm_kernel<false>,
                         cudaFuncAttributeMaxDynamicSharedMemorySize, (int)GEMM_SMEM);

    dim3 ggrid(ROWS / 128, WIDTH / 128);   // (256, 2)

    gemm_kernel<true><<<ggrid, 512, GEMM_SMEM>>>(tokens, emb, W1, b1, bufA, EMBED);
    rnn_kernel<true, false><<<2 * BATCH, 256>>>(bufA, U1, bufB,
                                                nullptr, nullptr, nullptr);
    gemm_kernel<false><<<ggrid, 512, GEMM_SMEM>>>(nullptr, bufB, W2, b2, bufA, WIDTH);
    rnn_kernel<false, true><<<2 * BATCH, 256>>>(bufA, U2, nullptr,
                                                Wd, bd, out);

    (void)in_sizes; (void)n_in; (void)out_size;
}

// round 16
// speedup vs baseline: 1.5936x; 1.0300x over previous
#include <cuda_runtime.h>
#include <math.h>
#include <stdint.h>

typedef unsigned long long ull;

// ---------------------------------------------------------------- constants
constexpr int BATCH = 64;
constexpr int SEQ   = 512;
constexpr int WIDTH = 256;   // hidden width
constexpr int EMBED = 512;   // 2*WIDTH
constexpr int ROWS  = BATCH * SEQ;   // 32768 GEMM rows

// ---------------------------------------------------------------- scratch
__device__ float g_bufA[BATCH * SEQ * WIDTH];
__device__ float g_bufB[BATCH * SEQ * WIDTH];

// ---------------------------------------------------------------- f32x2 helpers
__device__ __forceinline__ ull pk2(float lo, float hi) {
    ull r; asm("mov.b64 %0,{%1,%2};" : "=l"(r) : "f"(lo), "f"(hi)); return r;
}
__device__ __forceinline__ void up2(ull v, float& lo, float& hi) {
    asm("mov.b64 {%0,%1},%2;" : "=f"(lo), "=f"(hi) : "l"(v));
}
__device__ __forceinline__ ull ffma2(ull a, ull b, ull c) {
    ull d; asm("fma.rn.f32x2 %0,%1,%2,%3;" : "=l"(d) : "l"(a), "l"(b), "l"(c)); return d;
}
__device__ __forceinline__ uint32_t smem_u32(const void* p) {
    uint32_t a;
    asm("{ .reg .u64 t; cvta.to.shared.u64 t, %1; cvt.u32.u64 %0, t; }"
        : "=r"(a) : "l"(p));
    return a;
}
__device__ __forceinline__ void mbar_wait(uint32_t mb, uint32_t parity) {
    uint32_t done;
    asm volatile(
        "{\n\t.reg .pred p;\n\t"
        "mbarrier.try_wait.parity.acquire.cta.shared::cta.b64 p, [%1], %2;\n\t"
        "selp.b32 %0, 1, 0, p;\n\t}"
        : "=r"(done) : "r"(mb), "r"(parity) : "memory");
    if (!done) {
        asm volatile(
            "{\n\t.reg .pred P1;\n\t"
            "WL_%=:\n\t"
            "mbarrier.try_wait.parity.acquire.cta.shared::cta.b64 P1, [%0], %1, 0x989680;\n\t"
            "@P1 bra.uni WD_%=;\n\t"
            "bra.uni WL_%=;\n\t"
            "WD_%=:\n\t}"
            :: "r"(mb), "r"(parity) : "memory");
    }
}

// ============================================================================
// GEMM: C[R, 256] = A[R, K] @ Wm[K, 256] + bias
// 128x256 CTA tile (full N), 512 threads, 8x8 microtile, GK=16,
// register-prefetched tiles. FMA-bound: 12 LDS wf vs 64 FMA issue-cyc per
// warp per kk (R10 was 8 wf vs 32 cyc = crossbar co-bound).
// ============================================================================
constexpr int GK = 16;
constexpr int BS_STR = 264;   // Bs row stride (256 + 8 pad floats)
constexpr size_t GEMM_SMEM = (size_t)GK * 128 * 8      // ATu: 16 KB
                           + (size_t)GK * BS_STR * 4;  // Bs : 16.5 KB

template<bool GATHER>
__global__ void __launch_bounds__(512, 1)
gemm_kernel(const int* __restrict__ tokens, const float* __restrict__ A,
            const float* __restrict__ Wm, const float* __restrict__ bias,
            float* __restrict__ C, int K)
{
    extern __shared__ unsigned char gsm[];
    ull*   ATu = (ull*)gsm;                            // [GK][128] duplicated A
    float* Bs  = (float*)(gsm + (size_t)GK * 128 * 8); // [GK][BS_STR]

    const int tid = threadIdx.x;
    const int r0  = blockIdx.x * 128;

    // --- A loader: 128 rows x 16 k; 1 float4 per thread
    const int lrow = tid >> 2;            // 0..127
    const int lkq  = (tid & 3) * 4;       // 0,4,8,12
    const float* arow;
    if (GATHER) arow = A + (size_t)tokens[r0 + lrow] * (size_t)K;
    else        arow = A + (size_t)(r0 + lrow) * (size_t)K;

    // --- B loader: 16 k x 256 n; 2 float4 per thread
    const int bk = tid >> 5;              // 0..15
    const int bn = (tid & 31) * 8;        // 0..248

    // --- compute mapping: 16 row-groups x 32 col-groups, 8x8 microtile
    const int ty = tid >> 5;              // 0..15
    const int tx = tid & 31;              // 0..31
    const int cm = ty * 8;
    const int cn = tx * 8;

    ull acc[8][4];
    #pragma unroll
    for (int r = 0; r < 8; r++)
        #pragma unroll
        for (int c = 0; c < 4; c++) acc[r][c] = 0ull;

    // initial tile loads into registers
    float4 a4  = *(const float4*)(arow + lkq);
    float4 b0v = *(const float4*)(Wm + (size_t)bk * WIDTH + bn);
    float4 b1v = *(const float4*)(Wm + (size_t)bk * WIDTH + bn + 4);

    #pragma unroll 1
    for (int k0 = 0; k0 < K; k0 += GK) {
        __syncthreads();
        ATu[(lkq + 0) * 128 + lrow] = pk2(a4.x, a4.x);
        ATu[(lkq + 1) * 128 + lrow] = pk2(a4.y, a4.y);
        ATu[(lkq + 2) * 128 + lrow] = pk2(a4.z, a4.z);
        ATu[(lkq + 3) * 128 + lrow] = pk2(a4.w, a4.w);
        *(float4*)&Bs[bk * BS_STR + bn]     = b0v;
        *(float4*)&Bs[bk * BS_STR + bn + 4] = b1v;
        __syncthreads();

        // prefetch next tile (hidden by compute)
        if (k0 + GK < K) {
            a4  = *(const float4*)(arow + k0 + GK + lkq);
            b0v = *(const float4*)(Wm + (size_t)(k0 + GK + bk) * WIDTH + bn);
            b1v = *(const float4*)(Wm + (size_t)(k0 + GK + bk) * WIDTH + bn + 4);
        }

        #pragma unroll
        for (int kk = 0; kk < GK; kk++) {
            ulonglong2 bvA = *(const ulonglong2*)&Bs[kk * BS_STR + cn];
            ulonglong2 bvB = *(const ulonglong2*)&Bs[kk * BS_STR + cn + 4];
            const ull* arow_s = &ATu[kk * 128 + cm];
            ulonglong2 ad01 = *(const ulonglong2*)(arow_s + 0);  // broadcast
            ulonglong2 ad23 = *(const ulonglong2*)(arow_s + 2);
            ulonglong2 ad45 = *(const ulonglong2*)(arow_s + 4);
            ulonglong2 ad67 = *(const ulonglong2*)(arow_s + 6);
            ull ad[8] = { ad01.x, ad01.y, ad23.x, ad23.y,
                          ad45.x, ad45.y, ad67.x, ad67.y };
            #pragma unroll
            for (int r = 0; r < 8; r++) {
                acc[r][0] = ffma2(ad[r], bvA.x, acc[r][0]);
                acc[r][1] = ffma2(ad[r], bvA.y, acc[r][1]);
                acc[r][2] = ffma2(ad[r], bvB.x, acc[r][2]);
                acc[r][3] = ffma2(ad[r], bvB.y, acc[r][3]);
            }
        }
    }

    // epilogue: bias + store 8x8
    float bvals[8];
    #pragma unroll
    for (int c = 0; c < 8; c++) bvals[c] = bias[cn + c];
    #pragma unroll
    for (int r = 0; r < 8; r++) {
        float o[8];
        up2(acc[r][0], o[0], o[1]);
        up2(acc[r][1], o[2], o[3]);
        up2(acc[r][2], o[4], o[5]);
        up2(acc[r][3], o[6], o[7]);
        float4 w0 = make_float4(o[0] + bvals[0], o[1] + bvals[1],
                                o[2] + bvals[2], o[3] + bvals[3]);
        float4 w1 = make_float4(o[4] + bvals[4], o[5] + bvals[5],
                                o[6] + bvals[6], o[7] + bvals[7]);
        float* crow = &C[(size_t)(r0 + cm + r) * WIDTH + cn];
        *(float4*)(crow)     = w0;
        *(float4*)(crow + 4) = w1;
    }
}

// ============================================================================
// RNN scan, cluster-of-2 per batch row. (byte-identical to R14 — validated
// 336us, rel_err 5.878e-7)
//  - LOCAL half: plain STS + one __syncthreads per step (no mbar, no wait)
//  - PEER half: st.async -> peer's mbarP (512B tx), split-wait overlap
// ============================================================================
constexpr int HSTR = 264;    // floats per h buffer (256 + pad)

template<bool WRITE_SEQ, bool FINAL>
__global__ void __launch_bounds__(256, 1) __cluster_dims__(2, 1, 1)
rnn_kernel(const float* __restrict__ xw, const float* __restrict__ U,
           float* __restrict__ hs, const float* __restrict__ Wd,
           const float* __restrict__ bd, float* __restrict__ out)
{
    __shared__ __align__(16) float hbuf[2][HSTR];
    __shared__ __align__(8)  ull mbars[2];   // mbarP phase 0/1
    __shared__ float red[2 * WIDTH];

    const int tid = threadIdx.x;
    uint32_t rank;
    asm("mov.u32 %0, %%cluster_ctarank;" : "=r"(rank));
    const int b    = blockIdx.x >> 1;
    const int half = tid & 1;
    const int jl   = tid >> 1;             // 0..127
    const int j    = (int)rank * 128 + jl; // global column

    const int kbL = (int)rank * 128 + half * 64;        // locally-produced range
    const int kbP = (int)(rank ^ 1u) * 128 + half * 64; // peer-produced range

    ull uL[32], uP[32];
    #pragma unroll
    for (int m = 0; m < 32; m++) {
        uL[m] = pk2(U[(size_t)(kbL + 2 * m) * WIDTH + j],
                    U[(size_t)(kbL + 2 * m + 1) * WIDTH + j]);
        uP[m] = pk2(U[(size_t)(kbP + 2 * m) * WIDTH + j],
                    U[(size_t)(kbP + 2 * m + 1) * WIDTH + j]);
    }

    for (int i = tid; i < HSTR; i += 256) hbuf[0][i] = 0.0f;
    if (tid == 0) {
        asm volatile("mbarrier.init.shared.b64 [%0], %1;"
                     :: "r"(smem_u32(&mbars[0])), "r"(1) : "memory");
        asm volatile("mbarrier.init.shared.b64 [%0], %1;"
                     :: "r"(smem_u32(&mbars[1])), "r"(1) : "memory");
    }
    __syncthreads();
    asm volatile("barrier.cluster.arrive.aligned;" ::: "memory");
    asm volatile("barrier.cluster.wait.aligned;" ::: "memory");

    const uint32_t hbuf_u32 = smem_u32(&hbuf[0][0]);
    const uint32_t mbar_u32 = smem_u32(&mbars[0]);
    uint32_t peer_hbuf, peer_mbar;
    {
        uint32_t pr = rank ^ 1u;
        asm("mapa.shared::cluster.u32 %0, %1, %2;" : "=r"(peer_hbuf) : "r"(hbuf_u32), "r"(pr));
        asm("mapa.shared::cluster.u32 %0, %1, %2;" : "=r"(peer_mbar) : "r"(mbar_u32), "r"(pr));
    }

    const float* xb = xw + (size_t)b * SEQ * WIDTH + j;
    float xt_next = xb[0];

    #pragma unroll 1
    for (int t = 0; t < SEQ; t++) {
        const int rd = t & 1;
        const int wr = rd ^ 1;
        const uint32_t slot  = (uint32_t)(t & 1) * 8;
        const uint32_t pslot = (uint32_t)((t ^ 1) & 1) * 8;
        const uint32_t ppar  = (uint32_t)(((t - 1) >> 1) & 1);

        // arm this step's peer mbar (1 arrive + 512 expected bytes)
        if (tid == 0) {
            asm volatile("mbarrier.arrive.expect_tx.shared.b64 _, [%0], %1;"
                         :: "r"(mbar_u32 + slot), "r"(512) : "memory");
        }

        const float xt = xt_next;
        if (t + 1 < SEQ) xt_next = xb[(size_t)(t + 1) * WIDTH];

        ull a0 = 0ull, a1 = 0ull, a2 = 0ull, a3 = 0ull;

        // ---- phase 1: local-range pairs — NO WAIT (bar.sync published them)
        {
            const ull* hp = (const ull*)&hbuf[rd][0] + (kbL >> 1);
            #pragma unroll
            for (int m = 0; m < 32; m += 4) {
                ulonglong2 h01 = *(const ulonglong2*)(hp + m);
                ulonglong2 h23 = *(const ulonglong2*)(hp + m + 2);
                a0 = ffma2(h01.x, uL[m + 0], a0);
                a1 = ffma2(h01.y, uL[m + 1], a1);
                a2 = ffma2(h23.x, uL[m + 2], a2);
                a3 = ffma2(h23.y, uL[m + 3], a3);
            }
        }

        // ---- phase 2: peer-range pairs (DSMEM flight overlapped by phase 1)
        if (t > 0) mbar_wait(mbar_u32 + pslot, ppar);
        {
            const ull* hp = (const ull*)&hbuf[rd][0] + (kbP >> 1);
            #pragma unroll
            for (int m = 0; m < 32; m += 4) {
                ulonglong2 h01 = *(const ulonglong2*)(hp + m);
                ulonglong2 h23 = *(const ulonglong2*)(hp + m + 2);
                a0 = ffma2(h01.x, uP[m + 0], a0);
                a1 = ffma2(h01.y, uP[m + 1], a1);
                a2 = ffma2(h23.x, uP[m + 2], a2);
                a3 = ffma2(h23.y, uP[m + 3], a3);
            }
        }

        float s0, s1, s2, s3, s4, s5, s6, s7;
        up2(a0, s0, s1); up2(a1, s2, s3); up2(a2, s4, s5); up2(a3, s6, s7);
        float s = (((s0 + s1) + (s2 + s3)) + ((s4 + s5) + (s6 + s7)));
        s += __shfl_xor_sync(0xFFFFFFFFu, s, 1);   // combine k-halves

        const float e  = __expf(2.0f * (xt + s));
        const float hn = 1.0f - __fdividef(2.0f, e + 1.0f);

        if (half == 0) {
            // remote copy first (longest flight), then local STS
            const uint32_t off = (uint32_t)(wr * HSTR * 4 + j * 4);
            asm volatile(
                "st.async.shared::cluster.mbarrier::complete_tx::bytes.b32 [%0], %1, [%2];"
                :: "r"(peer_hbuf + off), "r"(__float_as_uint(hn)),
                   "r"(peer_mbar + slot) : "memory");
            hbuf[wr][j] = hn;                       // plain STS, local visibility
            if (WRITE_SEQ)
                hs[(size_t)b * SEQ * WIDTH + (size_t)t * WIDTH + j] = hn;
        }
        __syncthreads();   // publishes local STS; drains pending STS natively
    }

    // drain the final step's peer stores
    {
        const uint32_t fslot = (uint32_t)(511 & 1) * 8;
        const uint32_t fpar  = (uint32_t)((511 >> 1) & 1);
        mbar_wait(mbar_u32 + fslot, fpar);
    }

    if (FINAL && rank == 0) {
        const float h = hbuf[0][tid];   // t=511 wrote buffer 0
        red[tid]         = h * Wd[tid * 2 + 0];
        red[WIDTH + tid] = h * Wd[tid * 2 + 1];
        __syncthreads();
        #pragma unroll
        for (int sft = 128; sft > 0; sft >>= 1) {
            if (tid < sft) {
                red[tid]         += red[tid + sft];
                red[WIDTH + tid] += red[WIDTH + tid + sft];
            }
            __syncthreads();
        }
        if (tid == 0) {
            const float l0 = red[0] + bd[0];
            const float l1 = red[WIDTH] + bd[1];
            const float mx = fmaxf(l0, l1);
            const float e0 = expf(l0 - mx);
            const float e1 = expf(l1 - mx);
            const float inv = 1.0f / (e0 + e1);
            out[b * 2 + 0] = e0 * inv;
            out[b * 2 + 1] = e1 * inv;
        }
    }

    // no CTA exits while peer st.async traffic into its smem may be in flight
    asm volatile("barrier.cluster.arrive.aligned;" ::: "memory");
    asm volatile("barrier.cluster.wait.aligned;" ::: "memory");
}

// ============================================================================
// launcher
// ============================================================================
extern "C" void kernel_launch(void* const* d_in, const int* in_sizes, int n_in,
                              void* d_out, int out_size)
{
    const int*   tokens = (const int*)  d_in[0];
    const float* emb    = (const float*)d_in[1];
    const float* W1     = (const float*)d_in[2];
    const float* U1     = (const float*)d_in[3];
    const float* b1     = (const float*)d_in[4];
    const float* W2     = (const float*)d_in[5];
    const float* U2     = (const float*)d_in[6];
    const float* b2     = (const float*)d_in[7];
    const float* Wd     = (const float*)d_in[8];
    const float* bd     = (const float*)d_in[9];
    float* out = (float*)d_out;

    float* bufA; cudaGetSymbolAddress((void**)&bufA, g_bufA);
    float* bufB; cudaGetSymbolAddress((void**)&bufB, g_bufB);

    dim3 ggrid(ROWS / 128, 1);   // 256 CTAs, full N per CTA

    gemm_kernel<true><<<ggrid, 512, GEMM_SMEM>>>(tokens, emb, W1, b1, bufA, EMBED);
    rnn_kernel<true, false><<<2 * BATCH, 256>>>(bufA, U1, bufB,
                                                nullptr, nullptr, nullptr);
    gemm_kernel<false><<<ggrid, 512, GEMM_SMEM>>>(nullptr, bufB, W2, b2, bufA, WIDTH);
    rnn_kernel<false, true><<<2 * BATCH, 256>>>(bufA, U2, nullptr,
                                                Wd, bd, out);

    (void)in_sizes; (void)n_in; (void)out_size;
}